// round 1
// baseline (speedup 1.0000x reference)
#include <cuda_runtime.h>

// Problem constants
#define NB     4
#define LSEQ   4096
#define ROWS   16384        // NB * LSEQ
#define DIMV   512
#define HID2   2048         // 2 * HID
#define HIDV   1024
#define QKD    128
#define OUTD   8

// ------------------------- scratch (static device globals) -------------------
__device__ float g_normed[(size_t)ROWS * DIMV];           //  32 MB
__device__ float g_hidden[(size_t)ROWS * HID2];           // 128 MB  (v | gate)
__device__ float g_Z     [(size_t)ROWS * QKD];            //   8 MB
__device__ float g_q     [(size_t)ROWS * QKD];            //   8 MB
__device__ float g_k     [(size_t)ROWS * QKD];            //   8 MB
__device__ float g_A     [(size_t)NB * LSEQ * LSEQ];      // 268 MB
__device__ float g_V     [(size_t)ROWS * HIDV];           //  64 MB

// ------------------------------ LayerNorm ------------------------------------
__global__ void ln_kernel(const float* __restrict__ x, const float* __restrict__ g,
                          const float* __restrict__ b, float* __restrict__ o) {
    int row = blockIdx.x;
    int t = threadIdx.x;  // 128 threads, 4 floats each
    const float4* xr = (const float4*)(x + (size_t)row * DIMV);
    float4 xv = xr[t];
    float s  = xv.x + xv.y + xv.z + xv.w;
    float ss = xv.x*xv.x + xv.y*xv.y + xv.z*xv.z + xv.w*xv.w;
    #pragma unroll
    for (int off = 16; off; off >>= 1) {
        s  += __shfl_xor_sync(0xffffffffu, s,  off);
        ss += __shfl_xor_sync(0xffffffffu, ss, off);
    }
    __shared__ float sh_s[4], sh_ss[4];
    if ((t & 31) == 0) { sh_s[t >> 5] = s; sh_ss[t >> 5] = ss; }
    __syncthreads();
    s  = sh_s[0] + sh_s[1] + sh_s[2] + sh_s[3];
    ss = sh_ss[0] + sh_ss[1] + sh_ss[2] + sh_ss[3];
    float mu  = s * (1.0f / DIMV);
    float var = ss * (1.0f / DIMV) - mu * mu;
    float inv = rsqrtf(var + 1e-5f);
    float4 gv = ((const float4*)g)[t];
    float4 bv = ((const float4*)b)[t];
    float4 ov;
    ov.x = (xv.x - mu) * inv * gv.x + bv.x;
    ov.y = (xv.y - mu) * inv * gv.y + bv.y;
    ov.z = (xv.z - mu) * inv * gv.z + bv.z;
    ov.w = (xv.w - mu) * inv * gv.w + bv.w;
    ((float4*)(o + (size_t)row * DIMV))[t] = ov;
}

// ------------------------------ tiled SGEMM ----------------------------------
// C[M,N] = A[M,K] @ B  (BT=false: B is [K,N] row-major;  BT=true: B is [N,K] row-major)
// EPI: 0 = silu(acc + aux[n]);  1 = relu(acc*scale)^2;  2 = acc * aux[m*ldaux+n]
template<int EPI, bool BT>
__global__ void __launch_bounds__(256)
gemm_kernel(const float* __restrict__ Ag, const float* __restrict__ Bg,
            float* __restrict__ Cg,
            int M, int N, int K, int lda, int ldb, int ldc,
            size_t sA, size_t sB, size_t sC,
            const float* __restrict__ aux, int ldaux, size_t sAux,
            float scale)
{
    __shared__ float As[16][128];
    __shared__ float Bs[16][128];

    const float* A = Ag + blockIdx.z * sA;
    const float* B = Bg + blockIdx.z * sB;
    float*       C = Cg + blockIdx.z * sC;
    const float* ax = aux + blockIdx.z * sAux;

    int tid = threadIdx.x;
    int tx = tid & 15, ty = tid >> 4;
    int m0 = blockIdx.y * 128, n0 = blockIdx.x * 128;

    float acc[8][8];
    #pragma unroll
    for (int i = 0; i < 8; i++)
        #pragma unroll
        for (int j = 0; j < 8; j++) acc[i][j] = 0.0f;

    for (int k0 = 0; k0 < K; k0 += 16) {
        // load A tile (128 x 16), stored transposed in smem
        #pragma unroll
        for (int l = 0; l < 2; l++) {
            int idx = tid + l * 256;
            int r = idx >> 2, c4 = (idx & 3) * 4;
            float4 a = *(const float4*)(A + (size_t)(m0 + r) * lda + k0 + c4);
            As[c4 + 0][r] = a.x; As[c4 + 1][r] = a.y;
            As[c4 + 2][r] = a.z; As[c4 + 3][r] = a.w;
        }
        // load B tile (16 x 128)
        #pragma unroll
        for (int l = 0; l < 2; l++) {
            int idx = tid + l * 256;
            if (!BT) {
                int r = idx >> 5, c4 = (idx & 31) * 4;
                float4 bv = *(const float4*)(B + (size_t)(k0 + r) * ldb + n0 + c4);
                *(float4*)(&Bs[r][c4]) = bv;
            } else {
                int n = idx >> 2, k4 = (idx & 3) * 4;
                float4 bv = *(const float4*)(B + (size_t)(n0 + n) * ldb + k0 + k4);
                Bs[k4 + 0][n] = bv.x; Bs[k4 + 1][n] = bv.y;
                Bs[k4 + 2][n] = bv.z; Bs[k4 + 3][n] = bv.w;
            }
        }
        __syncthreads();
        #pragma unroll
        for (int kk = 0; kk < 16; kk++) {
            float ar[8], br[8];
            #pragma unroll
            for (int i = 0; i < 4; i++) {
                ar[i]     = As[kk][ty * 4 + i];
                ar[4 + i] = As[kk][64 + ty * 4 + i];
            }
            #pragma unroll
            for (int j = 0; j < 4; j++) {
                br[j]     = Bs[kk][tx * 4 + j];
                br[4 + j] = Bs[kk][64 + tx * 4 + j];
            }
            #pragma unroll
            for (int i = 0; i < 8; i++)
                #pragma unroll
                for (int j = 0; j < 8; j++)
                    acc[i][j] = fmaf(ar[i], br[j], acc[i][j]);
        }
        __syncthreads();
    }

    #pragma unroll
    for (int i = 0; i < 8; i++) {
        int m = m0 + (i < 4 ? ty * 4 + i : 64 + ty * 4 + (i - 4));
        #pragma unroll
        for (int j = 0; j < 8; j++) {
            int n = n0 + (j < 4 ? tx * 4 + j : 64 + tx * 4 + (j - 4));
            float v = acc[i][j];
            if (EPI == 0) {
                v += ax[n];
                v = v * (1.0f / (1.0f + __expf(-v)));      // silu
            } else if (EPI == 1) {
                float t = fmaxf(v * scale, 0.0f);
                v = t * t;                                  // relu(sim)^2
            } else {
                v *= ax[(size_t)m * ldaux + n];             // * gate
            }
            C[(size_t)m * ldc + n] = v;
        }
    }
}

// ---------------------------- q/k affine from Z ------------------------------
__global__ void qk_kernel(const float* __restrict__ Z,
                          const float* __restrict__ gamma, const float* __restrict__ beta,
                          float* __restrict__ q, float* __restrict__ k) {
    size_t idx = (size_t)blockIdx.x * blockDim.x + threadIdx.x;
    if (idx >= (size_t)ROWS * QKD) return;
    int d = (int)(idx & (QKD - 1));
    float z = Z[idx];
    q[idx] = z * gamma[d]        + beta[d];
    k[idx] = z * gamma[QKD + d]  + beta[QKD + d];
}

// ------------------------- output projection (1024 -> 8) ---------------------
__global__ void out_kernel(const float* __restrict__ Vg, const float* __restrict__ Wo,
                           const float* __restrict__ bo, float* __restrict__ out) {
    int row  = blockIdx.x * (blockDim.x >> 5) + (threadIdx.x >> 5);
    int lane = threadIdx.x & 31;
    const float* vr = Vg + (size_t)row * HIDV;
    float acc[OUTD];
    #pragma unroll
    for (int o = 0; o < OUTD; o++) acc[o] = 0.0f;
    for (int kk = lane; kk < HIDV; kk += 32) {
        float v = vr[kk];
        const float* w = Wo + (size_t)kk * OUTD;
        #pragma unroll
        for (int o = 0; o < OUTD; o++) acc[o] += v * w[o];
    }
    #pragma unroll
    for (int o = 0; o < OUTD; o++) {
        #pragma unroll
        for (int off = 16; off; off >>= 1)
            acc[o] += __shfl_xor_sync(0xffffffffu, acc[o], off);
    }
    if (lane < OUTD) out[(size_t)row * OUTD + lane] = acc[lane] + bo[lane];
}

// --------------------------------- launch ------------------------------------
extern "C" void kernel_launch(void* const* d_in, const int* in_sizes, int n_in,
                              void* d_out, int out_size) {
    const float* x     = (const float*)d_in[0];
    const float* ln_g  = (const float*)d_in[1];
    const float* ln_b  = (const float*)d_in[2];
    const float* Wh    = (const float*)d_in[3];
    const float* bh    = (const float*)d_in[4];
    const float* Wqk   = (const float*)d_in[5];
    const float* bqk   = (const float*)d_in[6];
    const float* gamma = (const float*)d_in[7];
    const float* beta  = (const float*)d_in[8];
    const float* Wo    = (const float*)d_in[9];
    const float* bo    = (const float*)d_in[10];
    float* out = (float*)d_out;

    float *normed, *hidden, *Z, *q, *k, *A, *V;
    cudaGetSymbolAddress((void**)&normed, g_normed);
    cudaGetSymbolAddress((void**)&hidden, g_hidden);
    cudaGetSymbolAddress((void**)&Z,      g_Z);
    cudaGetSymbolAddress((void**)&q,      g_q);
    cudaGetSymbolAddress((void**)&k,      g_k);
    cudaGetSymbolAddress((void**)&A,      g_A);
    cudaGetSymbolAddress((void**)&V,      g_V);

    // 1. LayerNorm
    ln_kernel<<<ROWS, 128>>>(x, ln_g, ln_b, normed);

    // 2. hidden = silu(normed @ Wh + bh)   [16384, 2048]
    gemm_kernel<0, false><<<dim3(HID2 / 128, ROWS / 128, 1), 256>>>(
        normed, Wh, hidden, ROWS, HID2, DIMV, DIMV, HID2, HID2,
        0, 0, 0, bh, 0, 0, 0.0f);

    // 3. Z = silu(normed @ Wqk + bqk)      [16384, 128]
    gemm_kernel<0, false><<<dim3(1, ROWS / 128, 1), 256>>>(
        normed, Wqk, Z, ROWS, QKD, DIMV, DIMV, QKD, QKD,
        0, 0, 0, bqk, 0, 0, 0.0f);

    // 4. q, k
    {
        size_t nel = (size_t)ROWS * QKD;
        qk_kernel<<<(unsigned)((nel + 255) / 256), 256>>>(Z, gamma, beta, q, k);
    }

    // 5. A = relu(q @ k^T / L)^2   per batch  [4096, 4096]
    gemm_kernel<1, true><<<dim3(LSEQ / 128, LSEQ / 128, NB), 256>>>(
        q, k, A, LSEQ, LSEQ, QKD, QKD, QKD, LSEQ,
        (size_t)LSEQ * QKD, (size_t)LSEQ * QKD, (size_t)LSEQ * LSEQ,
        bo /*unused*/, 0, 0, 1.0f / LSEQ);

    // 6. V = (A @ v) * gate   per batch  [4096, 1024]
    //    v = hidden[:, 0:1024], gate = hidden[:, 1024:2048]
    gemm_kernel<2, false><<<dim3(HIDV / 128, LSEQ / 128, NB), 256>>>(
        A, hidden, V, LSEQ, HIDV, LSEQ, LSEQ, HID2, HIDV,
        (size_t)LSEQ * LSEQ, (size_t)LSEQ * HID2, (size_t)LSEQ * HIDV,
        hidden + HIDV, HID2, (size_t)LSEQ * HID2, 0.0f);

    // 7. out = V @ Wo + bo   [16384, 8]
    out_kernel<<<ROWS / 8, 256>>>(V, Wo, bo, out);
}

// round 4
// speedup vs baseline: 2.4874x; 2.4874x over previous
#include <cuda_runtime.h>
#include <cstdint>

// Problem constants
#define NB     4
#define LSEQ   4096
#define ROWS   16384        // NB * LSEQ
#define DIMV   512
#define HID2   2048         // 2 * HID
#define HIDV   1024
#define QKD    128
#define OUTD   8

// ------------------------- scratch (static device globals) -------------------
__device__ float g_normed[(size_t)ROWS * DIMV];           //  32 MB
__device__ float g_hidden[(size_t)ROWS * HID2];           // 128 MB  (v | gate)
__device__ float g_Z     [(size_t)ROWS * QKD];            //   8 MB
__device__ float g_q     [(size_t)ROWS * QKD];            //   8 MB
__device__ float g_k     [(size_t)ROWS * QKD];            //   8 MB
__device__ float g_A     [(size_t)NB * LSEQ * LSEQ];      // 268 MB
__device__ float g_V     [(size_t)ROWS * HIDV];           //  64 MB

// ------------------------------ helpers --------------------------------------
__device__ __forceinline__ uint32_t f2tf32(float f) {
    uint32_t r;
    asm("cvt.rna.tf32.f32 %0, %1;" : "=r"(r) : "f"(f));
    return r;
}

__device__ __forceinline__ void mma_tf32(float* c, const uint32_t* a, const uint32_t* b) {
    asm volatile(
        "mma.sync.aligned.m16n8k8.row.col.f32.tf32.tf32.f32 "
        "{%0,%1,%2,%3},{%4,%5,%6,%7},{%8,%9},{%0,%1,%2,%3};"
        : "+f"(c[0]), "+f"(c[1]), "+f"(c[2]), "+f"(c[3])
        : "r"(a[0]), "r"(a[1]), "r"(a[2]), "r"(a[3]), "r"(b[0]), "r"(b[1]));
}

// ------------------------------ LayerNorm ------------------------------------
__global__ void ln_kernel(const float* __restrict__ x, const float* __restrict__ g,
                          const float* __restrict__ b, float* __restrict__ o) {
    int row = blockIdx.x;
    int t = threadIdx.x;  // 128 threads, 4 floats each
    const float4* xr = (const float4*)(x + (size_t)row * DIMV);
    float4 xv = xr[t];
    float s  = xv.x + xv.y + xv.z + xv.w;
    float ss = xv.x*xv.x + xv.y*xv.y + xv.z*xv.z + xv.w*xv.w;
    #pragma unroll
    for (int off = 16; off; off >>= 1) {
        s  += __shfl_xor_sync(0xffffffffu, s,  off);
        ss += __shfl_xor_sync(0xffffffffu, ss, off);
    }
    __shared__ float sh_s[4], sh_ss[4];
    if ((t & 31) == 0) { sh_s[t >> 5] = s; sh_ss[t >> 5] = ss; }
    __syncthreads();
    s  = sh_s[0] + sh_s[1] + sh_s[2] + sh_s[3];
    ss = sh_ss[0] + sh_ss[1] + sh_ss[2] + sh_ss[3];
    float mu  = s * (1.0f / DIMV);
    float var = ss * (1.0f / DIMV) - mu * mu;
    float inv = rsqrtf(var + 1e-5f);
    float4 gv = ((const float4*)g)[t];
    float4 bv = ((const float4*)b)[t];
    float4 ov;
    ov.x = (xv.x - mu) * inv * gv.x + bv.x;
    ov.y = (xv.y - mu) * inv * gv.y + bv.y;
    ov.z = (xv.z - mu) * inv * gv.z + bv.z;
    ov.w = (xv.w - mu) * inv * gv.w + bv.w;
    ((float4*)(o + (size_t)row * DIMV))[t] = ov;
}

// --------------------------- tf32 tensor-core GEMM ---------------------------
// C[M,N] = A[M,K] @ B   (BT=false: B is [K,N] row-major; BT=true: B is [N,K])
// CTA tile 128x128, BK=32, 8 warps, warp tile 64x32 (4x4 m16n8k8 frags).
// EPI: 0 = silu(acc + aux[n]);  1 = relu(acc*scale)^2;  2 = acc * aux[m*ldaux+n]
template<int EPI, bool BT>
__global__ void __launch_bounds__(256)
tmma_gemm(const float* __restrict__ Ag, const float* __restrict__ Bg,
          float* __restrict__ Cg,
          int M, int N, int K, int lda, int ldb, int ldc,
          size_t sA, size_t sB, size_t sC,
          const float* __restrict__ aux, int ldaux, size_t sAux,
          float scale)
{
    __shared__ float As[128][36];   // [m][k], pad 36 -> conflict-free frag loads
    __shared__ float Bs[32][132];   // [k][n], pad 132

    const float* A = Ag + blockIdx.z * sA;
    const float* B = Bg + blockIdx.z * sB;
    float*       C = Cg + blockIdx.z * sC;
    const float* ax = aux + blockIdx.z * sAux;

    const int tid  = threadIdx.x;
    const int warp = tid >> 5;
    const int lane = tid & 31;
    const int grp  = lane >> 2;   // 0..7
    const int tig  = lane & 3;    // 0..3
    const int mw   = (warp >> 2) * 64;  // warp m-offset (0,64)
    const int nw   = (warp & 3) * 32;   // warp n-offset (0,32,64,96)
    const int m0 = blockIdx.y * 128, n0 = blockIdx.x * 128;

    float acc[4][4][4];
    #pragma unroll
    for (int mi = 0; mi < 4; mi++)
        #pragma unroll
        for (int ni = 0; ni < 4; ni++)
            #pragma unroll
            for (int r = 0; r < 4; r++) acc[mi][ni][r] = 0.0f;

    // global-load register staging
    float4 ra[4], rb[4];

    auto load_A = [&](int k0) {
        #pragma unroll
        for (int l = 0; l < 4; l++) {
            int fid = tid + l * 256;
            int r = fid >> 3, c = (fid & 7) * 4;
            ra[l] = *(const float4*)(A + (size_t)(m0 + r) * lda + k0 + c);
        }
    };
    auto load_B = [&](int k0) {
        #pragma unroll
        for (int l = 0; l < 4; l++) {
            int fid = tid + l * 256;
            if (!BT) {
                int r = fid >> 5, c = (fid & 31) * 4;
                rb[l] = *(const float4*)(B + (size_t)(k0 + r) * ldb + n0 + c);
            } else {
                int n = fid >> 3, kc = (fid & 7) * 4;
                rb[l] = *(const float4*)(B + (size_t)(n0 + n) * ldb + k0 + kc);
            }
        }
    };
    auto store_tiles = [&]() {
        #pragma unroll
        for (int l = 0; l < 4; l++) {
            int fid = tid + l * 256;
            int r = fid >> 3, c = (fid & 7) * 4;
            float4 v = ra[l];
            As[r][c + 0] = __uint_as_float(f2tf32(v.x));
            As[r][c + 1] = __uint_as_float(f2tf32(v.y));
            As[r][c + 2] = __uint_as_float(f2tf32(v.z));
            As[r][c + 3] = __uint_as_float(f2tf32(v.w));
        }
        #pragma unroll
        for (int l = 0; l < 4; l++) {
            int fid = tid + l * 256;
            float4 v = rb[l];
            if (!BT) {
                int r = fid >> 5, c = (fid & 31) * 4;
                Bs[r][c + 0] = __uint_as_float(f2tf32(v.x));
                Bs[r][c + 1] = __uint_as_float(f2tf32(v.y));
                Bs[r][c + 2] = __uint_as_float(f2tf32(v.z));
                Bs[r][c + 3] = __uint_as_float(f2tf32(v.w));
            } else {
                int n = fid >> 3, kc = (fid & 7) * 4;
                Bs[kc + 0][n] = __uint_as_float(f2tf32(v.x));
                Bs[kc + 1][n] = __uint_as_float(f2tf32(v.y));
                Bs[kc + 2][n] = __uint_as_float(f2tf32(v.z));
                Bs[kc + 3][n] = __uint_as_float(f2tf32(v.w));
            }
        }
    };

    const int niter = K / 32;
    load_A(0);
    load_B(0);

    for (int it = 0; it < niter; it++) {
        store_tiles();
        __syncthreads();
        if (it + 1 < niter) {       // prefetch next tile during compute
            load_A((it + 1) * 32);
            load_B((it + 1) * 32);
        }
        #pragma unroll
        for (int ks = 0; ks < 32; ks += 8) {
            uint32_t afr[4][4], bfr[4][2];
            #pragma unroll
            for (int mi = 0; mi < 4; mi++) {
                int r = mw + mi * 16 + grp;
                afr[mi][0] = __float_as_uint(As[r][ks + tig]);
                afr[mi][1] = __float_as_uint(As[r + 8][ks + tig]);
                afr[mi][2] = __float_as_uint(As[r][ks + tig + 4]);
                afr[mi][3] = __float_as_uint(As[r + 8][ks + tig + 4]);
            }
            #pragma unroll
            for (int ni = 0; ni < 4; ni++) {
                int c = nw + ni * 8 + grp;
                bfr[ni][0] = __float_as_uint(Bs[ks + tig][c]);
                bfr[ni][1] = __float_as_uint(Bs[ks + tig + 4][c]);
            }
            #pragma unroll
            for (int mi = 0; mi < 4; mi++)
                #pragma unroll
                for (int ni = 0; ni < 4; ni++)
                    mma_tf32(acc[mi][ni], afr[mi], bfr[ni]);
        }
        __syncthreads();
    }

    // ------------------------------ epilogue ---------------------------------
    #pragma unroll
    for (int mi = 0; mi < 4; mi++) {
        #pragma unroll
        for (int half = 0; half < 2; half++) {
            int m = m0 + mw + mi * 16 + grp + half * 8;
            #pragma unroll
            for (int ni = 0; ni < 4; ni++) {
                int n = n0 + nw + ni * 8 + tig * 2;
                float v0 = acc[mi][ni][half * 2 + 0];
                float v1 = acc[mi][ni][half * 2 + 1];
                if (EPI == 0) {
                    v0 += ax[n];     v1 += ax[n + 1];
                    v0 = v0 / (1.0f + __expf(-v0));
                    v1 = v1 / (1.0f + __expf(-v1));
                } else if (EPI == 1) {
                    float t0 = fmaxf(v0 * scale, 0.0f);
                    float t1 = fmaxf(v1 * scale, 0.0f);
                    v0 = t0 * t0; v1 = t1 * t1;
                } else {
                    v0 *= ax[(size_t)m * ldaux + n];
                    v1 *= ax[(size_t)m * ldaux + n + 1];
                }
                *(float2*)(C + (size_t)m * ldc + n) = make_float2(v0, v1);
            }
        }
    }
}

// ---------------------------- q/k affine from Z ------------------------------
__global__ void qk_kernel(const float* __restrict__ Z,
                          const float* __restrict__ gamma, const float* __restrict__ beta,
                          float* __restrict__ q, float* __restrict__ k) {
    size_t idx = (size_t)blockIdx.x * blockDim.x + threadIdx.x;
    if (idx >= (size_t)ROWS * QKD) return;
    int d = (int)(idx & (QKD - 1));
    float z = Z[idx];
    q[idx] = z * gamma[d]       + beta[d];
    k[idx] = z * gamma[QKD + d] + beta[QKD + d];
}

// ------------------------- output projection (1024 -> 8) ---------------------
__global__ void out_kernel(const float* __restrict__ Vg, const float* __restrict__ Wo,
                           const float* __restrict__ bo, float* __restrict__ out) {
    int row  = blockIdx.x * (blockDim.x >> 5) + (threadIdx.x >> 5);
    int lane = threadIdx.x & 31;
    const float* vr = Vg + (size_t)row * HIDV;
    float acc[OUTD];
    #pragma unroll
    for (int o = 0; o < OUTD; o++) acc[o] = 0.0f;
    for (int kk = lane; kk < HIDV; kk += 32) {
        float v = vr[kk];
        const float* w = Wo + (size_t)kk * OUTD;
        #pragma unroll
        for (int o = 0; o < OUTD; o++) acc[o] += v * w[o];
    }
    #pragma unroll
    for (int o = 0; o < OUTD; o++) {
        #pragma unroll
        for (int off = 16; off; off >>= 1)
            acc[o] += __shfl_xor_sync(0xffffffffu, acc[o], off);
    }
    if (lane < OUTD) out[(size_t)row * OUTD + lane] = acc[lane] + bo[lane];
}

// --------------------------------- launch ------------------------------------
extern "C" void kernel_launch(void* const* d_in, const int* in_sizes, int n_in,
                              void* d_out, int out_size) {
    const float* x     = (const float*)d_in[0];
    const float* ln_g  = (const float*)d_in[1];
    const float* ln_b  = (const float*)d_in[2];
    const float* Wh    = (const float*)d_in[3];
    const float* bh    = (const float*)d_in[4];
    const float* Wqk   = (const float*)d_in[5];
    const float* bqk   = (const float*)d_in[6];
    const float* gamma = (const float*)d_in[7];
    const float* beta  = (const float*)d_in[8];
    const float* Wo    = (const float*)d_in[9];
    const float* bo    = (const float*)d_in[10];
    float* out = (float*)d_out;

    float *normed, *hidden, *Z, *q, *k, *A, *V;
    cudaGetSymbolAddress((void**)&normed, g_normed);
    cudaGetSymbolAddress((void**)&hidden, g_hidden);
    cudaGetSymbolAddress((void**)&Z,      g_Z);
    cudaGetSymbolAddress((void**)&q,      g_q);
    cudaGetSymbolAddress((void**)&k,      g_k);
    cudaGetSymbolAddress((void**)&A,      g_A);
    cudaGetSymbolAddress((void**)&V,      g_V);

    // 1. LayerNorm
    ln_kernel<<<ROWS, 128>>>(x, ln_g, ln_b, normed);

    // 2. hidden = silu(normed @ Wh + bh)   [16384, 2048]
    tmma_gemm<0, false><<<dim3(HID2 / 128, ROWS / 128, 1), 256>>>(
        normed, Wh, hidden, ROWS, HID2, DIMV, DIMV, HID2, HID2,
        0, 0, 0, bh, 0, 0, 0.0f);

    // 3. Z = silu(normed @ Wqk + bqk)      [16384, 128]
    tmma_gemm<0, false><<<dim3(1, ROWS / 128, 1), 256>>>(
        normed, Wqk, Z, ROWS, QKD, DIMV, DIMV, QKD, QKD,
        0, 0, 0, bqk, 0, 0, 0.0f);

    // 4. q, k
    {
        size_t nel = (size_t)ROWS * QKD;
        qk_kernel<<<(unsigned)((nel + 255) / 256), 256>>>(Z, gamma, beta, q, k);
    }

    // 5. A = relu(q @ k^T / L)^2   per batch  [4096, 4096]
    tmma_gemm<1, true><<<dim3(LSEQ / 128, LSEQ / 128, NB), 256>>>(
        q, k, A, LSEQ, LSEQ, QKD, QKD, QKD, LSEQ,
        (size_t)LSEQ * QKD, (size_t)LSEQ * QKD, (size_t)LSEQ * LSEQ,
        bo /*unused*/, 0, 0, 1.0f / LSEQ);

    // 6. V = (A @ v) * gate   per batch  [4096, 1024]
    tmma_gemm<2, false><<<dim3(HIDV / 128, LSEQ / 128, NB), 256>>>(
        A, hidden, V, LSEQ, HIDV, LSEQ, LSEQ, HID2, HIDV,
        (size_t)LSEQ * LSEQ, (size_t)LSEQ * HID2, (size_t)LSEQ * HIDV,
        hidden + HIDV, HID2, (size_t)LSEQ * HID2, 0.0f);

    // 7. out = V @ Wo + bo   [16384, 8]
    out_kernel<<<ROWS / 8, 256>>>(V, Wo, bo, out);
}

// round 6
// speedup vs baseline: 3.6232x; 1.4567x over previous
#include <cuda_runtime.h>
#include <cstdint>

// Problem constants
#define NB     4
#define LSEQ   4096
#define ROWS   16384
#define DIMV   512
#define HID2   2048
#define HIDV   1024
#define QKD    128
#define OUTD   8

// ------------------------- scratch (static device globals) -------------------
__device__ float g_normed[(size_t)ROWS * DIMV];      //  32 MB (tf32-rounded)
__device__ float g_WhR   [(size_t)DIMV * HID2];      //   4 MB (tf32-rounded)
__device__ float g_WqkR  [(size_t)DIMV * QKD];       // 256 KB (tf32-rounded)
__device__ float g_hidden[(size_t)ROWS * HID2];      // 128 MB (v tf32 | gate fp32)
__device__ float g_Z     [(size_t)ROWS * QKD];       //   8 MB
__device__ float g_q     [(size_t)ROWS * QKD];       //   8 MB (tf32)
__device__ float g_k     [(size_t)ROWS * QKD];       //   8 MB (tf32)
__device__ float g_A     [(size_t)NB * LSEQ * LSEQ]; // 268 MB (tf32)
__device__ float g_V     [(size_t)ROWS * HIDV];      //  64 MB

// ------------------------------ helpers --------------------------------------
__device__ __forceinline__ uint32_t f2tf32(float f) {
    uint32_t r;
    asm("cvt.rna.tf32.f32 %0, %1;" : "=r"(r) : "f"(f));
    return r;
}
__device__ __forceinline__ float tf32r(float f) { return __uint_as_float(f2tf32(f)); }

__device__ __forceinline__ uint32_t smem_u32(const void* p) {
    uint32_t a;
    asm("{ .reg .u64 t; cvta.to.shared.u64 t, %1; cvt.u32.u64 %0, t; }" : "=r"(a) : "l"(p));
    return a;
}
__device__ __forceinline__ void cp16(uint32_t s, const float* g) {
    asm volatile("cp.async.cg.shared.global [%0], [%1], 16;" :: "r"(s), "l"(g));
}
#define CP_COMMIT() asm volatile("cp.async.commit_group;" ::: "memory")
#define CP_WAIT0()  asm volatile("cp.async.wait_group 0;" ::: "memory")
#define CP_WAIT1()  asm volatile("cp.async.wait_group 1;" ::: "memory")

__device__ __forceinline__ void mma_tf32(float* c, const uint32_t* a, const uint32_t* b) {
    asm volatile(
        "mma.sync.aligned.m16n8k8.row.col.f32.tf32.tf32.f32 "
        "{%0,%1,%2,%3},{%4,%5,%6,%7},{%8,%9},{%0,%1,%2,%3};"
        : "+f"(c[0]), "+f"(c[1]), "+f"(c[2]), "+f"(c[3])
        : "r"(a[0]), "r"(a[1]), "r"(a[2]), "r"(a[3]), "r"(b[0]), "r"(b[1]));
}

// ------------------------------ LayerNorm (tf32 out) -------------------------
__global__ void ln_kernel(const float* __restrict__ x, const float* __restrict__ g,
                          const float* __restrict__ b, float* __restrict__ o) {
    int row = blockIdx.x;
    int t = threadIdx.x;
    const float4* xr = (const float4*)(x + (size_t)row * DIMV);
    float4 xv = xr[t];
    float s  = xv.x + xv.y + xv.z + xv.w;
    float ss = xv.x*xv.x + xv.y*xv.y + xv.z*xv.z + xv.w*xv.w;
    #pragma unroll
    for (int off = 16; off; off >>= 1) {
        s  += __shfl_xor_sync(0xffffffffu, s,  off);
        ss += __shfl_xor_sync(0xffffffffu, ss, off);
    }
    __shared__ float sh_s[4], sh_ss[4];
    if ((t & 31) == 0) { sh_s[t >> 5] = s; sh_ss[t >> 5] = ss; }
    __syncthreads();
    s  = sh_s[0] + sh_s[1] + sh_s[2] + sh_s[3];
    ss = sh_ss[0] + sh_ss[1] + sh_ss[2] + sh_ss[3];
    float mu  = s * (1.0f / DIMV);
    float var = ss * (1.0f / DIMV) - mu * mu;
    float inv = rsqrtf(var + 1e-5f);
    float4 gv = ((const float4*)g)[t];
    float4 bv = ((const float4*)b)[t];
    float4 ov;
    ov.x = tf32r((xv.x - mu) * inv * gv.x + bv.x);
    ov.y = tf32r((xv.y - mu) * inv * gv.y + bv.y);
    ov.z = tf32r((xv.z - mu) * inv * gv.z + bv.z);
    ov.w = tf32r((xv.w - mu) * inv * gv.w + bv.w);
    ((float4*)(o + (size_t)row * DIMV))[t] = ov;
}

// --------------------------- tf32 rounding copy ------------------------------
__global__ void round_tf32(const float* __restrict__ s, float* __restrict__ d, int n) {
    int i = blockIdx.x * blockDim.x + threadIdx.x;
    if (i < n) d[i] = tf32r(s[i]);
}

// --------------------------- tf32 tensor-core GEMM ---------------------------
// C[M,N] = A[M,K] @ B   (BT=false: B is [K,N] row-major; BT=true: B is [N,K])
// All MMA operands pre-rounded to tf32 by producers -> HW truncation is exact.
// CTA tile 128x128, BK=32, 2-stage cp.async pipeline, 8 warps, warp tile 64x32.
// EPI 0: v = silu(acc + aux[n]);  tf32-round when n < HIDV (v half / Z), raw otherwise (gate)
// EPI 1: tf32(relu(acc*scale)^2)
// EPI 2: acc * aux[m*ldaux + n]
template<int EPI, bool BT>
__global__ void __launch_bounds__(256, 2)
tmma_gemm(const float* __restrict__ Ag, const float* __restrict__ Bg,
          float* __restrict__ Cg, int K, int lda, int ldb, int ldc,
          size_t sA, size_t sB, size_t sC,
          const float* __restrict__ aux, int ldaux, size_t sAux, float scale)
{
    constexpr int ASTG = 128 * 36;                 // floats per A stage (pitch 36)
    constexpr int BPITCH = BT ? 36 : 136;
    constexpr int BSTG = BT ? (128 * 36) : (32 * 136);

    extern __shared__ float sm[];
    float* AsBase = sm;                  // 2 stages
    float* BsBase = sm + 2 * ASTG;       // 2 stages
    const uint32_t sbA = smem_u32(AsBase);
    const uint32_t sbB = smem_u32(BsBase);

    const float* A = Ag + blockIdx.z * sA;
    const float* B = Bg + blockIdx.z * sB;
    float*       C = Cg + blockIdx.z * sC;
    const float* ax = aux + blockIdx.z * sAux;

    const int tid  = threadIdx.x;
    const int warp = tid >> 5;
    const int lane = tid & 31;
    const int grp  = lane >> 2;
    const int tig  = lane & 3;
    const int mw   = (warp >> 2) * 64;
    const int nw   = (warp & 3) * 32;
    const int m0 = blockIdx.y * 128, n0 = blockIdx.x * 128;

    float acc[4][4][4];
    #pragma unroll
    for (int mi = 0; mi < 4; mi++)
        #pragma unroll
        for (int ni = 0; ni < 4; ni++)
            #pragma unroll
            for (int r = 0; r < 4; r++) acc[mi][ni][r] = 0.0f;

    auto load_stage = [&](int st, int k0) {
        // A tile: 128 x 32 floats = 1024 16B chunks, 4/thread
        #pragma unroll
        for (int l = 0; l < 4; l++) {
            int fid = tid + l * 256;
            int r = fid >> 3, ch = fid & 7;
            cp16(sbA + (uint32_t)(st * ASTG + r * 36 + ch * 4) * 4,
                 A + (size_t)(m0 + r) * lda + k0 + ch * 4);
        }
        #pragma unroll
        for (int l = 0; l < 4; l++) {
            int fid = tid + l * 256;
            if (!BT) {   // 32 x 128 floats
                int r = fid >> 5, ch = fid & 31;
                cp16(sbB + (uint32_t)(st * BSTG + r * BPITCH + ch * 4) * 4,
                     B + (size_t)(k0 + r) * ldb + n0 + ch * 4);
            } else {     // 128 x 32 floats
                int n = fid >> 3, ch = fid & 7;
                cp16(sbB + (uint32_t)(st * BSTG + n * BPITCH + ch * 4) * 4,
                     B + (size_t)(n0 + n) * ldb + k0 + ch * 4);
            }
        }
        CP_COMMIT();
    };

    const int niter = K / 32;
    load_stage(0, 0);

    for (int it = 0; it < niter; it++) {
        if (it + 1 < niter) { load_stage((it + 1) & 1, (it + 1) * 32); CP_WAIT1(); }
        else                { CP_WAIT0(); }
        __syncthreads();

        const float* As = AsBase + (it & 1) * ASTG;
        const float* Bs = BsBase + (it & 1) * BSTG;

        #pragma unroll
        for (int ks = 0; ks < 32; ks += 8) {
            uint32_t afr[4][4], bfr[4][2];
            #pragma unroll
            for (int mi = 0; mi < 4; mi++) {
                int r = mw + mi * 16 + grp;
                afr[mi][0] = __float_as_uint(As[r * 36 + ks + tig]);
                afr[mi][1] = __float_as_uint(As[(r + 8) * 36 + ks + tig]);
                afr[mi][2] = __float_as_uint(As[r * 36 + ks + tig + 4]);
                afr[mi][3] = __float_as_uint(As[(r + 8) * 36 + ks + tig + 4]);
            }
            #pragma unroll
            for (int ni = 0; ni < 4; ni++) {
                int c = nw + ni * 8 + grp;
                if (!BT) {
                    bfr[ni][0] = __float_as_uint(Bs[(ks + tig) * BPITCH + c]);
                    bfr[ni][1] = __float_as_uint(Bs[(ks + tig + 4) * BPITCH + c]);
                } else {
                    bfr[ni][0] = __float_as_uint(Bs[c * BPITCH + ks + tig]);
                    bfr[ni][1] = __float_as_uint(Bs[c * BPITCH + ks + tig + 4]);
                }
            }
            #pragma unroll
            for (int mi = 0; mi < 4; mi++)
                #pragma unroll
                for (int ni = 0; ni < 4; ni++)
                    mma_tf32(acc[mi][ni], afr[mi], bfr[ni]);
        }
        __syncthreads();
    }

    // ------------------------------ epilogue ---------------------------------
    #pragma unroll
    for (int mi = 0; mi < 4; mi++) {
        #pragma unroll
        for (int half = 0; half < 2; half++) {
            int m = m0 + mw + mi * 16 + grp + half * 8;
            #pragma unroll
            for (int ni = 0; ni < 4; ni++) {
                int n = n0 + nw + ni * 8 + tig * 2;
                float v0 = acc[mi][ni][half * 2 + 0];
                float v1 = acc[mi][ni][half * 2 + 1];
                if (EPI == 0) {
                    v0 += ax[n];     v1 += ax[n + 1];
                    v0 = v0 / (1.0f + __expf(-v0));
                    v1 = v1 / (1.0f + __expf(-v1));
                    if (n < HIDV)     v0 = tf32r(v0);   // v half / Z: feeds next MMA
                    if (n + 1 < HIDV) v1 = tf32r(v1);
                } else if (EPI == 1) {
                    float t0 = fmaxf(v0 * scale, 0.0f);
                    float t1 = fmaxf(v1 * scale, 0.0f);
                    v0 = tf32r(t0 * t0); v1 = tf32r(t1 * t1);
                } else {
                    v0 *= ax[(size_t)m * ldaux + n];
                    v1 *= ax[(size_t)m * ldaux + n + 1];
                }
                *(float2*)(C + (size_t)m * ldc + n) = make_float2(v0, v1);
            }
        }
    }
}

// ---------------------------- q/k affine from Z (tf32 out) -------------------
__global__ void qk_kernel(const float* __restrict__ Z,
                          const float* __restrict__ gamma, const float* __restrict__ beta,
                          float* __restrict__ q, float* __restrict__ k) {
    size_t idx = (size_t)blockIdx.x * blockDim.x + threadIdx.x;
    if (idx >= (size_t)ROWS * QKD) return;
    int d = (int)(idx & (QKD - 1));
    float z = Z[idx];
    q[idx] = tf32r(z * gamma[d]       + beta[d]);
    k[idx] = tf32r(z * gamma[QKD + d] + beta[QKD + d]);
}

// ------------------------- output projection (1024 -> 8) ---------------------
__global__ void out_kernel(const float* __restrict__ Vg, const float* __restrict__ Wo,
                           const float* __restrict__ bo, float* __restrict__ out) {
    int row  = blockIdx.x * (blockDim.x >> 5) + (threadIdx.x >> 5);
    int lane = threadIdx.x & 31;
    const float* vr = Vg + (size_t)row * HIDV;
    float acc[OUTD];
    #pragma unroll
    for (int o = 0; o < OUTD; o++) acc[o] = 0.0f;
    for (int kk = lane; kk < HIDV; kk += 32) {
        float v = vr[kk];
        const float* w = Wo + (size_t)kk * OUTD;
        #pragma unroll
        for (int o = 0; o < OUTD; o++) acc[o] += v * w[o];
    }
    #pragma unroll
    for (int o = 0; o < OUTD; o++) {
        #pragma unroll
        for (int off = 16; off; off >>= 1)
            acc[o] += __shfl_xor_sync(0xffffffffu, acc[o], off);
    }
    if (lane < OUTD) out[(size_t)row * OUTD + lane] = acc[lane] + bo[lane];
}

// --------------------------------- launch ------------------------------------
extern "C" void kernel_launch(void* const* d_in, const int* in_sizes, int n_in,
                              void* d_out, int out_size) {
    const float* x     = (const float*)d_in[0];
    const float* ln_g  = (const float*)d_in[1];
    const float* ln_b  = (const float*)d_in[2];
    const float* Wh    = (const float*)d_in[3];
    const float* bh    = (const float*)d_in[4];
    const float* Wqk   = (const float*)d_in[5];
    const float* bqk   = (const float*)d_in[6];
    const float* gamma = (const float*)d_in[7];
    const float* beta  = (const float*)d_in[8];
    const float* Wo    = (const float*)d_in[9];
    const float* bo    = (const float*)d_in[10];
    float* out = (float*)d_out;

    float *normed, *WhR, *WqkR, *hidden, *Z, *q, *k, *A, *V;
    cudaGetSymbolAddress((void**)&normed, g_normed);
    cudaGetSymbolAddress((void**)&WhR,    g_WhR);
    cudaGetSymbolAddress((void**)&WqkR,   g_WqkR);
    cudaGetSymbolAddress((void**)&hidden, g_hidden);
    cudaGetSymbolAddress((void**)&Z,      g_Z);
    cudaGetSymbolAddress((void**)&q,      g_q);
    cudaGetSymbolAddress((void**)&k,      g_k);
    cudaGetSymbolAddress((void**)&A,      g_A);
    cudaGetSymbolAddress((void**)&V,      g_V);

    // dynamic smem: A 2*128*36*4 = 36864 B; B nonBT 2*32*136*4 = 34816 B; BT 36864 B
    const int SM_NBT = 36864 + 34816;   // 71680
    const int SM_BT  = 36864 + 36864;   // 73728
    static bool attr_done = false;
    if (!attr_done) {
        cudaFuncSetAttribute(tmma_gemm<0,false>, cudaFuncAttributeMaxDynamicSharedMemorySize, SM_NBT);
        cudaFuncSetAttribute(tmma_gemm<1,true >, cudaFuncAttributeMaxDynamicSharedMemorySize, SM_BT);
        cudaFuncSetAttribute(tmma_gemm<2,false>, cudaFuncAttributeMaxDynamicSharedMemorySize, SM_NBT);
        attr_done = true;
    }

    // 0. tf32-round the weights (once per launch; cheap)
    round_tf32<<<(DIMV * HID2 + 255) / 256, 256>>>(Wh,  WhR,  DIMV * HID2);
    round_tf32<<<(DIMV * QKD  + 255) / 256, 256>>>(Wqk, WqkR, DIMV * QKD);

    // 1. LayerNorm (tf32-rounded output)
    ln_kernel<<<ROWS, 128>>>(x, ln_g, ln_b, normed);

    // 2. hidden = silu(normed @ Wh + bh)   [16384, 2048]  (v half tf32, gate fp32)
    tmma_gemm<0, false><<<dim3(HID2 / 128, ROWS / 128, 1), 256, SM_NBT>>>(
        normed, WhR, hidden, DIMV, DIMV, HID2, HID2,
        0, 0, 0, bh, 0, 0, 0.0f);

    // 3. Z = silu(normed @ Wqk + bqk)      [16384, 128]
    tmma_gemm<0, false><<<dim3(1, ROWS / 128, 1), 256, SM_NBT>>>(
        normed, WqkR, Z, DIMV, DIMV, QKD, QKD,
        0, 0, 0, bqk, 0, 0, 0.0f);

    // 4. q, k (tf32-rounded)
    {
        size_t nel = (size_t)ROWS * QKD;
        qk_kernel<<<(unsigned)((nel + 255) / 256), 256>>>(Z, gamma, beta, q, k);
    }

    // 5. A = tf32(relu(q @ k^T / L)^2)   per batch  [4096, 4096]
    tmma_gemm<1, true><<<dim3(LSEQ / 128, LSEQ / 128, NB), 256, SM_BT>>>(
        q, k, A, QKD, QKD, QKD, LSEQ,
        (size_t)LSEQ * QKD, (size_t)LSEQ * QKD, (size_t)LSEQ * LSEQ,
        bo /*unused*/, 0, 0, 1.0f / LSEQ);

    // 6. V = (A @ v) * gate   per batch  [4096, 1024]
    tmma_gemm<2, false><<<dim3(HIDV / 128, LSEQ / 128, NB), 256, SM_NBT>>>(
        A, hidden, V, LSEQ, LSEQ, HID2, HIDV,
        (size_t)LSEQ * LSEQ, (size_t)LSEQ * HID2, (size_t)LSEQ * HIDV,
        hidden + HIDV, HID2, (size_t)LSEQ * HID2, 0.0f);

    // 7. out = V @ Wo + bo
    out_kernel<<<ROWS / 8, 256>>>(V, Wo, bo, out);
}